// round 1
// baseline (speedup 1.0000x reference)
#include <cuda_runtime.h>
#include <cuda_bf16.h>
#include <math_constants.h>

#define N_STATES   65536
#define LATENT     512
#define WARPS_TOT  2048          // 256 blocks * 8 warps
#define ROWS_PER_W (N_STATES / WARPS_TOT)   // 32
#define NBLK_COMB  64            // combine blocks, each folds 32 warp-partials

// ---- static scratch (no allocation allowed) ----
__device__ float g_warp_m[WARPS_TOT];
__device__ float g_warp_Z[WARPS_TOT];
__device__ float g_warp_q[(size_t)WARPS_TOT * LATENT];   // 4 MB
__device__ float g_part_q[NBLK_COMB * LATENT];
__device__ float g_part_Z[NBLK_COMB];
__device__ float g_M;

// ======================================================================
// Pass 1: one warp streams 32 rows. For each row:
//   - coalesced load of the 4 KB row (lane l holds float4 j = l + 32k)
//   - dist = sum_d (imu-mu)^2 + (isig-sig)^2   (butterfly-reduced)
//   - online softmin update of (m, Z, q[512 distributed across lanes])
// ======================================================================
__global__ __launch_bounds__(256, 2)
void quant_pass1(const float* __restrict__ imu,
                 const float* __restrict__ isg,
                 const float4* __restrict__ onst,   // row = 256 float4
                 float* __restrict__ dists_out)
{
    const int lane = threadIdx.x & 31;
    const int wid  = threadIdx.x >> 5;
    const int gw   = blockIdx.x * 8 + wid;

    // per-lane copy of the input stats, laid out to match the float4 loads:
    // float4 j covers d = 2j (x:mu, y:sig) and d = 2j+1 (z:mu, w:sig)
    float4 a[8];
#pragma unroll
    for (int k = 0; k < 8; k++) {
        int j  = lane + 32 * k;
        int d0 = 2 * j;
        a[k] = make_float4(imu[d0], isg[d0], imu[d0 + 1], isg[d0 + 1]);
    }

    float m = CUDART_INF_F;
    float Z = 0.f;
    float q[16];
#pragma unroll
    for (int i = 0; i < 16; i++) q[i] = 0.f;

    const int row0 = gw * ROWS_PER_W;

    for (int r = 0; r < ROWS_PER_W; r++) {
        const float4* p = onst + (size_t)(row0 + r) * 256 + lane;
        float4 v[8];
#pragma unroll
        for (int k = 0; k < 8; k++) v[k] = __ldg(p + 32 * k);

        float s = 0.f;
#pragma unroll
        for (int k = 0; k < 8; k++) {
            float dx = v[k].x - a[k].x; s = fmaf(dx, dx, s);
            float dy = v[k].y - a[k].y; s = fmaf(dy, dy, s);
            float dz = v[k].z - a[k].z; s = fmaf(dz, dz, s);
            float dw = v[k].w - a[k].w; s = fmaf(dw, dw, s);
        }
#pragma unroll
        for (int o = 16; o > 0; o >>= 1)
            s += __shfl_xor_sync(0xffffffffu, s, o);

        if (lane == 0) dists_out[row0 + r] = s;

        // online softmin: weights exp(m - d_i), m = running min
        float w;
        if (s < m) {
            float f = __expf(s - m);     // first row: exp(-inf) = 0
            Z *= f;
#pragma unroll
            for (int i = 0; i < 16; i++) q[i] *= f;
            m = s;
            w = 1.f;
        } else {
            w = __expf(m - s);
        }
        Z += w;
#pragma unroll
        for (int k = 0; k < 8; k++) {
            q[2 * k]     = fmaf(w, v[k].x, q[2 * k]);
            q[2 * k + 1] = fmaf(w, v[k].z, q[2 * k + 1]);
        }
    }

    if (lane == 0) { g_warp_m[gw] = m; g_warp_Z[gw] = Z; }
    float* qb = g_warp_q + (size_t)gw * LATENT;
#pragma unroll
    for (int k = 0; k < 8; k++) {
        int j = lane + 32 * k;
        qb[2 * j]     = q[2 * k];
        qb[2 * j + 1] = q[2 * k + 1];
    }
}

// ======================================================================
// K2: global min of the 2048 warp mins
// ======================================================================
__global__ void quant_min()
{
    __shared__ float sm[256];
    int t = threadIdx.x;
    float v = CUDART_INF_F;
#pragma unroll
    for (int i = 0; i < WARPS_TOT / 256; i++)
        v = fminf(v, g_warp_m[t + 256 * i]);
    sm[t] = v;
    __syncthreads();
    for (int o = 128; o > 0; o >>= 1) {
        if (t < o) sm[t] = fminf(sm[t], sm[t + o]);
        __syncthreads();
    }
    if (t == 0) g_M = sm[0];
}

// ======================================================================
// K3: 64 blocks, each folds 32 warp partials (rescaled to global min)
// ======================================================================
__global__ __launch_bounds__(512)
void quant_combine()
{
    __shared__ float f[32];
    const int b = blockIdx.x;
    const int t = threadIdx.x;
    const float M = g_M;

    if (t < 32) {
        int w = b * 32 + t;
        float fw = __expf(M - g_warp_m[w]);   // <= 1
        f[t] = fw;
        float zw = g_warp_Z[w] * fw;
#pragma unroll
        for (int o = 16; o > 0; o >>= 1)
            zw += __shfl_xor_sync(0xffffffffu, zw, o);
        if (t == 0) g_part_Z[b] = zw;
    }
    __syncthreads();

    float acc = 0.f;
#pragma unroll 8
    for (int i = 0; i < 32; i++) {
        int w = b * 32 + i;
        acc = fmaf(g_warp_q[(size_t)w * LATENT + t], f[i], acc);
    }
    g_part_q[b * LATENT + t] = acc;
}

// ======================================================================
// K4: final fold -> quantised[512], losses (identical by stop_gradient)
// ======================================================================
__global__ __launch_bounds__(512)
void quant_final(const float* __restrict__ imu, float* __restrict__ out)
{
    const int t = threadIdx.x;

    float qsum = 0.f;
#pragma unroll 8
    for (int b = 0; b < NBLK_COMB; b++)
        qsum += g_part_q[b * LATENT + t];

    __shared__ float zbuf[64];
    if (t < 64) zbuf[t] = g_part_Z[t];
    __syncthreads();
    if (t == 0) {
        float z = 0.f;
        for (int i = 0; i < 64; i++) z += zbuf[i];
        zbuf[0] = z;
    }
    __syncthreads();
    const float Z = zbuf[0];

    const float quant = qsum / Z;
    out[t] = quant;

    float diff = quant - imu[t];
    float e = diff * diff;
#pragma unroll
    for (int o = 16; o > 0; o >>= 1)
        e += __shfl_xor_sync(0xffffffffu, e, o);

    __shared__ float red[16];
    if ((t & 31) == 0) red[t >> 5] = e;
    __syncthreads();
    if (t == 0) {
        float s = 0.f;
#pragma unroll
        for (int i = 0; i < 16; i++) s += red[i];
        float loss = s / (float)LATENT;
        out[LATENT]     = loss;   // loss_enc
        out[LATENT + 1] = loss;   // loss_ref (stop_gradient => same value)
    }
}

// ======================================================================
extern "C" void kernel_launch(void* const* d_in, const int* in_sizes, int n_in,
                              void* d_out, int out_size)
{
    const float*  imu  = (const float*)d_in[0];   // input_mu  [512]
    const float*  isg  = (const float*)d_in[1];   // input_sig [512]
    const float4* onst = (const float4*)d_in[2];  // on_states [65536,512,2]
    float* out = (float*)d_out;                   // [512 | 1 | 1 | 65536]

    quant_pass1<<<WARPS_TOT / 8, 256>>>(imu, isg, onst, out + LATENT + 2);
    quant_min<<<1, 256>>>();
    quant_combine<<<NBLK_COMB, 512>>>();
    quant_final<<<1, 512>>>(imu, out);
}

// round 2
// speedup vs baseline: 1.0558x; 1.0558x over previous
#include <cuda_runtime.h>
#include <cuda_bf16.h>
#include <math_constants.h>

#define N_STATES   65536
#define LATENT     512
#define NBLK       296                    // 2 blocks per SM on 148-SM GB300
#define WARPS_PB   8
#define NW         (NBLK * WARPS_PB)      // 2368 warps, grid-stride over rows

// ---- static scratch (no allocation allowed) ----
__device__ float g_blk_m[NBLK];
__device__ float g_blk_Z[NBLK];
__device__ float g_blk_q[NBLK * LATENT];  // ~606 KB, L2-resident

// ======================================================================
// Pass 1: warp-per-row streaming with online softmin, then an in-block
// fold of the 8 warps' (m, Z, q) states -> ONE partial per block.
// ======================================================================
__global__ __launch_bounds__(256, 2)
void quant_pass1(const float* __restrict__ imu,
                 const float* __restrict__ isg,
                 const float4* __restrict__ onst,   // row = 256 float4
                 float* __restrict__ dists_out)
{
    const int lane = threadIdx.x & 31;
    const int wid  = threadIdx.x >> 5;
    const int gw   = blockIdx.x * WARPS_PB + wid;

    // per-lane input stats matching the float4 load layout:
    // float4 j covers d=2j (x:mu, y:sig) and d=2j+1 (z:mu, w:sig)
    float4 a[8];
#pragma unroll
    for (int k = 0; k < 8; k++) {
        int j  = lane + 32 * k;
        int d0 = 2 * j;
        a[k] = make_float4(imu[d0], isg[d0], imu[d0 + 1], isg[d0 + 1]);
    }

    float m = CUDART_INF_F;
    float Z = 0.f;
    float q[16];
#pragma unroll
    for (int i = 0; i < 16; i++) q[i] = 0.f;

    for (int row = gw; row < N_STATES; row += NW) {
        const float4* p = onst + (size_t)row * 256 + lane;
        float4 v[8];
#pragma unroll
        for (int k = 0; k < 8; k++) v[k] = __ldg(p + 32 * k);

        float s = 0.f;
#pragma unroll
        for (int k = 0; k < 8; k++) {
            float dx = v[k].x - a[k].x; s = fmaf(dx, dx, s);
            float dy = v[k].y - a[k].y; s = fmaf(dy, dy, s);
            float dz = v[k].z - a[k].z; s = fmaf(dz, dz, s);
            float dw = v[k].w - a[k].w; s = fmaf(dw, dw, s);
        }
#pragma unroll
        for (int o = 16; o > 0; o >>= 1)
            s += __shfl_xor_sync(0xffffffffu, s, o);

        if (lane == 0) dists_out[row] = s;

        // online softmin: weights exp(m - d_i), m = running min
        float w;
        if (s < m) {
            float f = __expf(s - m);     // first row: exp(-inf) = 0
            Z *= f;
#pragma unroll
            for (int i = 0; i < 16; i++) q[i] *= f;
            m = s;
            w = 1.f;
        } else {
            w = __expf(m - s);
        }
        Z += w;
#pragma unroll
        for (int k = 0; k < 8; k++) {
            q[2 * k]     = fmaf(w, v[k].x, q[2 * k]);
            q[2 * k + 1] = fmaf(w, v[k].z, q[2 * k + 1]);
        }
    }

    // ---- in-block fold of 8 warp states -> one (m, Z, q[512]) partial ----
    __shared__ float s_m[WARPS_PB];
    __shared__ float s_Z[WARPS_PB];
    __shared__ float s_q[WARPS_PB][LATENT];

    if (lane == 0) s_m[wid] = m;
    __syncthreads();

    float mB = s_m[0];
#pragma unroll
    for (int w2 = 1; w2 < WARPS_PB; w2++) mB = fminf(mB, s_m[w2]);

    const float fw = __expf(mB - m);     // <= 1
    if (lane == 0) s_Z[wid] = Z * fw;
#pragma unroll
    for (int k = 0; k < 8; k++) {
        int j = lane + 32 * k;
        s_q[wid][2 * j]     = q[2 * k]     * fw;
        s_q[wid][2 * j + 1] = q[2 * k + 1] * fw;
    }
    __syncthreads();

    const int t = threadIdx.x;
#pragma unroll
    for (int h = 0; h < 2; h++) {
        int c = t + 256 * h;
        float acc = 0.f;
#pragma unroll
        for (int w2 = 0; w2 < WARPS_PB; w2++) acc += s_q[w2][c];
        g_blk_q[blockIdx.x * LATENT + c] = acc;
    }
    if (t == 0) {
        float zz = 0.f;
#pragma unroll
        for (int w2 = 0; w2 < WARPS_PB; w2++) zz += s_Z[w2];
        g_blk_Z[blockIdx.x] = zz;
        g_blk_m[blockIdx.x] = mB;
    }
}

// ======================================================================
// Fused combine: global min -> rescale -> float4 fold -> quantised+losses.
// One block of 1024 threads. Everything hits L2. Fully deterministic
// (fixed-order reductions, no float atomics).
// ======================================================================
__global__ __launch_bounds__(1024)
void quant_combine(const float* __restrict__ imu, float* __restrict__ out)
{
    __shared__ float  f[NBLK];
    __shared__ float  zf[NBLK];
    __shared__ float  red[32];
    __shared__ float  sMZ[2];                 // [0]=M, [1]=Z
    __shared__ float4 sacc[8][LATENT / 4];    // 16 KB

    const int t    = threadIdx.x;
    const int lane = t & 31;

    // ---- global min over 296 block-mins ----
    float v = (t < NBLK) ? g_blk_m[t] : CUDART_INF_F;
#pragma unroll
    for (int o = 16; o > 0; o >>= 1)
        v = fminf(v, __shfl_xor_sync(0xffffffffu, v, o));
    if (lane == 0) red[t >> 5] = v;
    __syncthreads();
    if (t < 32) {
        float v2 = red[t];
#pragma unroll
        for (int o = 16; o > 0; o >>= 1)
            v2 = fminf(v2, __shfl_xor_sync(0xffffffffu, v2, o));
        if (t == 0) sMZ[0] = v2;
    }
    __syncthreads();
    const float M = sMZ[0];

    // ---- rescale factors + per-partial Z ----
    if (t < NBLK) {
        float fb = __expf(M - g_blk_m[t]);
        f[t]  = fb;
        zf[t] = g_blk_Z[t] * fb;
    }
    __syncthreads();

    // deterministic Z: one warp, fixed accumulation order
    if (t < 32) {
        float z = 0.f;
#pragma unroll
        for (int k = 0; k < (NBLK + 31) / 32; k++) {
            int i = t + 32 * k;
            if (i < NBLK) z += zf[i];
        }
#pragma unroll
        for (int o = 16; o > 0; o >>= 1)
            z += __shfl_xor_sync(0xffffffffu, z, o);
        if (t == 0) sMZ[1] = z;
    }

    // ---- vectorized fold: 8 groups x 128 float4-columns ----
    const int j = t & 127;        // float4 column
    const int g = t >> 7;         // group 0..7
    const float4* q4 = (const float4*)g_blk_q;
    float4 acc = make_float4(0.f, 0.f, 0.f, 0.f);
    for (int b = g; b < NBLK; b += 8) {
        float  fb = f[b];
        float4 x  = q4[b * (LATENT / 4) + j];
        acc.x = fmaf(fb, x.x, acc.x);
        acc.y = fmaf(fb, x.y, acc.y);
        acc.z = fmaf(fb, x.z, acc.z);
        acc.w = fmaf(fb, x.w, acc.w);
    }
    sacc[g][j] = acc;
    __syncthreads();

    const float Z = sMZ[1];

    if (t < 128) {
        float4 s = sacc[0][t];
#pragma unroll
        for (int g2 = 1; g2 < 8; g2++) {
            float4 x = sacc[g2][t];
            s.x += x.x; s.y += x.y; s.z += x.z; s.w += x.w;
        }
        float4 qn = make_float4(s.x / Z, s.y / Z, s.z / Z, s.w / Z);
        ((float4*)out)[t] = qn;

        float4 im = ((const float4*)imu)[t];
        float dx = qn.x - im.x, dy = qn.y - im.y;
        float dz = qn.z - im.z, dw = qn.w - im.w;
        float e = dx * dx + dy * dy + dz * dz + dw * dw;
#pragma unroll
        for (int o = 16; o > 0; o >>= 1)
            e += __shfl_xor_sync(0xffffffffu, e, o);
        if (lane == 0) red[t >> 5] = e;   // warps 0..3
    }
    __syncthreads();
    if (t == 0) {
        float s = red[0] + red[1] + red[2] + red[3];
        float loss = s / (float)LATENT;
        out[LATENT]     = loss;   // loss_enc
        out[LATENT + 1] = loss;   // loss_ref (stop_gradient => same value)
    }
}

// ======================================================================
extern "C" void kernel_launch(void* const* d_in, const int* in_sizes, int n_in,
                              void* d_out, int out_size)
{
    const float*  imu  = (const float*)d_in[0];   // input_mu  [512]
    const float*  isg  = (const float*)d_in[1];   // input_sig [512]
    const float4* onst = (const float4*)d_in[2];  // on_states [65536,512,2]
    float* out = (float*)d_out;                   // [512 | 1 | 1 | 65536]

    quant_pass1<<<NBLK, 256>>>(imu, isg, onst, out + LATENT + 2);
    quant_combine<<<1, 1024>>>(imu, out);
}

// round 3
// speedup vs baseline: 1.1231x; 1.0637x over previous
#include <cuda_runtime.h>
#include <cuda_bf16.h>
#include <math_constants.h>

#define N_STATES   65536
#define LATENT     512
#define NCOL       (LATENT / 4)           // 128 float4 columns
#define NBLK       296                    // 2 blocks per SM on 148-SM GB300
#define WARPS_PB   8
#define NW         (NBLK * WARPS_PB)      // 2368 warps, grid-stride over rows

// ---- static scratch (no allocation allowed) ----
__device__ float    g_blk_m[NBLK];
__device__ float    g_blk_Z[NBLK];
__device__ float    g_blk_q[NBLK * LATENT];  // ~606 KB, L2-resident
__device__ unsigned g_ctr = 0;               // combine completion ticket

// ======================================================================
// Pass 1: warp-per-row streaming with online softmin, then an in-block
// fold of the 8 warps' (m, Z, q) states -> ONE partial per block.
// (At HBM roofline: 256 MB in ~34 us.)
// ======================================================================
__global__ __launch_bounds__(256, 2)
void quant_pass1(const float* __restrict__ imu,
                 const float* __restrict__ isg,
                 const float4* __restrict__ onst,   // row = 256 float4
                 float* __restrict__ dists_out)
{
    const int lane = threadIdx.x & 31;
    const int wid  = threadIdx.x >> 5;
    const int gw   = blockIdx.x * WARPS_PB + wid;

    // per-lane input stats matching the float4 load layout:
    // float4 j covers d=2j (x:mu, y:sig) and d=2j+1 (z:mu, w:sig)
    float4 a[8];
#pragma unroll
    for (int k = 0; k < 8; k++) {
        int j  = lane + 32 * k;
        int d0 = 2 * j;
        a[k] = make_float4(imu[d0], isg[d0], imu[d0 + 1], isg[d0 + 1]);
    }

    float m = CUDART_INF_F;
    float Z = 0.f;
    float q[16];
#pragma unroll
    for (int i = 0; i < 16; i++) q[i] = 0.f;

    for (int row = gw; row < N_STATES; row += NW) {
        const float4* p = onst + (size_t)row * 256 + lane;
        float4 v[8];
#pragma unroll
        for (int k = 0; k < 8; k++) v[k] = __ldg(p + 32 * k);

        float s = 0.f;
#pragma unroll
        for (int k = 0; k < 8; k++) {
            float dx = v[k].x - a[k].x; s = fmaf(dx, dx, s);
            float dy = v[k].y - a[k].y; s = fmaf(dy, dy, s);
            float dz = v[k].z - a[k].z; s = fmaf(dz, dz, s);
            float dw = v[k].w - a[k].w; s = fmaf(dw, dw, s);
        }
#pragma unroll
        for (int o = 16; o > 0; o >>= 1)
            s += __shfl_xor_sync(0xffffffffu, s, o);

        if (lane == 0) dists_out[row] = s;

        // online softmin: weights exp(m - d_i), m = running min
        float w;
        if (s < m) {
            float f = __expf(s - m);     // first row: exp(-inf) = 0
            Z *= f;
#pragma unroll
            for (int i = 0; i < 16; i++) q[i] *= f;
            m = s;
            w = 1.f;
        } else {
            w = __expf(m - s);
        }
        Z += w;
#pragma unroll
        for (int k = 0; k < 8; k++) {
            q[2 * k]     = fmaf(w, v[k].x, q[2 * k]);
            q[2 * k + 1] = fmaf(w, v[k].z, q[2 * k + 1]);
        }
    }

    // ---- in-block fold of 8 warp states -> one (m, Z, q[512]) partial ----
    __shared__ float s_m[WARPS_PB];
    __shared__ float s_Z[WARPS_PB];
    __shared__ float s_q[WARPS_PB][LATENT];

    if (lane == 0) s_m[wid] = m;
    __syncthreads();

    float mB = s_m[0];
#pragma unroll
    for (int w2 = 1; w2 < WARPS_PB; w2++) mB = fminf(mB, s_m[w2]);

    const float fw = __expf(mB - m);     // <= 1
    if (lane == 0) s_Z[wid] = Z * fw;
#pragma unroll
    for (int k = 0; k < 8; k++) {
        int j = lane + 32 * k;
        s_q[wid][2 * j]     = q[2 * k]     * fw;
        s_q[wid][2 * j + 1] = q[2 * k + 1] * fw;
    }
    __syncthreads();

    const int t = threadIdx.x;
#pragma unroll
    for (int h = 0; h < 2; h++) {
        int c = t + 256 * h;
        float acc = 0.f;
#pragma unroll
        for (int w2 = 0; w2 < WARPS_PB; w2++) acc += s_q[w2][c];
        g_blk_q[blockIdx.x * LATENT + c] = acc;
    }
    if (t == 0) {
        float zz = 0.f;
#pragma unroll
        for (int w2 = 0; w2 < WARPS_PB; w2++) zz += s_Z[w2];
        g_blk_Z[blockIdx.x] = zz;
        g_blk_m[blockIdx.x] = mB;
    }
}

// ======================================================================
// Column-parallel combine: 128 blocks, one float4 column each.
// Each block redundantly computes M and Z (296 tiny L2 loads), folds its
// own column, writes 4 dims of quantised. The LAST block to finish
// computes both losses from the completed output (deterministic).
// ======================================================================
__global__ __launch_bounds__(256)
void quant_combine(const float* __restrict__ imu, float* __restrict__ out)
{
    __shared__ float  sm[256];
    __shared__ float  sf[NBLK];
    __shared__ float  sz[256];
    __shared__ float4 sv[256];
    __shared__ int    s_last;

    const int t = threadIdx.x;
    const int j = blockIdx.x;          // float4 column 0..127

    // ---- global min over block mins (tree reduce: deterministic) ----
    float mv = CUDART_INF_F;
    for (int b = t; b < NBLK; b += 256) mv = fminf(mv, g_blk_m[b]);
    sm[t] = mv;
    __syncthreads();
#pragma unroll
    for (int o = 128; o > 0; o >>= 1) {
        if (t < o) sm[t] = fminf(sm[t], sm[t + o]);
        __syncthreads();
    }
    const float M = sm[0];

    // ---- rescale factors + Z (fixed-order tree: deterministic) ----
    float zv = 0.f;
    for (int b = t; b < NBLK; b += 256) {
        float fb = __expf(M - g_blk_m[b]);
        sf[b] = fb;
        zv = fmaf(g_blk_Z[b], fb, zv);
    }
    sz[t] = zv;
    __syncthreads();
#pragma unroll
    for (int o = 128; o > 0; o >>= 1) {
        if (t < o) sz[t] += sz[t + o];
        __syncthreads();
    }
    const float Z = sz[0];

    // ---- fold this block's column over all partials ----
    const float4* q4 = (const float4*)g_blk_q;
    float4 acc = make_float4(0.f, 0.f, 0.f, 0.f);
    for (int b = t; b < NBLK; b += 256) {
        float  fb = sf[b];
        float4 x  = q4[(size_t)b * NCOL + j];
        acc.x = fmaf(fb, x.x, acc.x);
        acc.y = fmaf(fb, x.y, acc.y);
        acc.z = fmaf(fb, x.z, acc.z);
        acc.w = fmaf(fb, x.w, acc.w);
    }
    sv[t] = acc;
    __syncthreads();
#pragma unroll
    for (int o = 128; o > 0; o >>= 1) {
        if (t < o) {
            float4 a2 = sv[t], b2 = sv[t + o];
            a2.x += b2.x; a2.y += b2.y; a2.z += b2.z; a2.w += b2.w;
            sv[t] = a2;
        }
        __syncthreads();
    }
    if (t == 0) {
        float4 r = sv[0];
        ((float4*)out)[j] = make_float4(r.x / Z, r.y / Z, r.z / Z, r.w / Z);
    }

    // ---- last-block-done: losses from the finalized quantised vector ----
    __threadfence();
    if (t == 0) s_last = (atomicAdd(&g_ctr, 1u) == NCOL - 1);
    __syncthreads();

    if (s_last) {
        float e = 0.f;
        for (int d = t; d < LATENT; d += 256) {
            float qd   = __ldcg(&out[d]);      // bypass L1: other SMs wrote these
            float diff = qd - imu[d];
            e = fmaf(diff, diff, e);
        }
        sz[t] = e;
        __syncthreads();
#pragma unroll
        for (int o = 128; o > 0; o >>= 1) {
            if (t < o) sz[t] += sz[t + o];
            __syncthreads();
        }
        if (t == 0) {
            float loss = sz[0] / (float)LATENT;
            out[LATENT]     = loss;   // loss_enc
            out[LATENT + 1] = loss;   // loss_ref (stop_gradient => same value)
            g_ctr = 0;                // reset for next graph replay
        }
    }
}

// ======================================================================
extern "C" void kernel_launch(void* const* d_in, const int* in_sizes, int n_in,
                              void* d_out, int out_size)
{
    const float*  imu  = (const float*)d_in[0];   // input_mu  [512]
    const float*  isg  = (const float*)d_in[1];   // input_sig [512]
    const float4* onst = (const float4*)d_in[2];  // on_states [65536,512,2]
    float* out = (float*)d_out;                   // [512 | 1 | 1 | 65536]

    quant_pass1<<<NBLK, 256>>>(imu, isg, onst, out + LATENT + 2);
    quant_combine<<<NCOL, 256>>>(imu, out);
}